// round 2
// baseline (speedup 1.0000x reference)
#include <cuda_runtime.h>
#include <cuda_bf16.h>

#define Nn  8
#define Cc  64
#define Hh  128
#define Ww  512
#define CoN 64
#define HW  (Hh * Ww)      // 65536
#define NOFF 18            // 2 * K * K

typedef unsigned long long ull;

// Packed fp32x2 FMA: d = a * b + d (lanewise on 2 floats in a 64-bit reg)
#define FMA_F32X2(d, a, b) \
    asm("fma.rn.f32x2 %0, %1, %2, %0;" : "+l"(d) : "l"(a), "l"(b))

#define PACK2(dst, lo, hi) \
    asm("mov.b64 %0, {%1, %2};" : "=l"(dst) : "f"(lo), "f"(hi))

#define PACK2_DUP(dst, v) \
    asm("mov.b64 %0, {%1, %1};" : "=l"(dst) : "f"(v))

#define UNPACK2(lo, hi, src) \
    asm("mov.b64 {%0, %1}, %2;" : "=f"(lo), "=f"(hi) : "l"(src))

// Scratch: offsets from stage-1 conv, and transposed deform weights [t][c][o].
__device__ float g_off[(size_t)Nn * NOFF * HW];   // ~36 MB
__device__ float g_wt[9 * 64 * 64];               // 144 KB

// ---------------------------------------------------------------------------
// Kernel 0: transpose w_def [o][c][3][3] -> g_wt [t][c][o] (one-time, tiny)
// ---------------------------------------------------------------------------
__global__ void wt_transpose_kernel(const float* __restrict__ wdef) {
    int idx = blockIdx.x * 256 + threadIdx.x;
    if (idx < 9 * 64 * 64) {
        int t = idx % 9;
        int c = (idx / 9) % 64;
        int o = idx / (9 * 64);
        g_wt[(t * 64 + c) * 64 + o] = wdef[idx];
    }
}

// ---------------------------------------------------------------------------
// Kernel 1: offset-predicting 3x3 conv (C=64 -> 18), pad 1, stride 1.
// 18 accumulators packed into 9 f32x2 pairs. Weights in smem, row stride
// 20 floats (10 ull) so pairs load as LDS.64.
// ---------------------------------------------------------------------------
__global__ void __launch_bounds__(128) offset_conv_kernel(
    const float* __restrict__ xin,
    const float* __restrict__ woff,
    const float* __restrict__ boff)
{
    __shared__ __align__(16) ull sw2[576 * 10];    // 46080 B: [(c*9+tap)][9 pairs + pad]
    float* swf = (float*)sw2;
    int tid = threadIdx.x;

    for (int m = tid; m < 18 * 576; m += 128) {
        int t = m / 576;
        int r = m - t * 576;          // c*9 + tap
        swf[r * 20 + t] = woff[m];
    }
    __syncthreads();

    int xo = blockIdx.x * 128 + tid;
    int y  = blockIdx.y;
    int n  = blockIdx.z;

    ull acc2[9];
#pragma unroll
    for (int q = 0; q < 9; q++) {
        float lo = __ldg(&boff[2 * q]);
        float hi = __ldg(&boff[2 * q + 1]);
        PACK2(acc2[q], lo, hi);
    }

    const float* xb = xin + (size_t)n * Cc * HW;

    for (int c = 0; c < Cc; c++) {
        const float* xc = xb + c * HW;
#pragma unroll
        for (int i = 0; i < 3; i++) {
            int yy = y + i - 1;
            if (yy < 0 || yy >= Hh) continue;
            const float* row = xc + yy * Ww;
#pragma unroll
            for (int j = 0; j < 3; j++) {
                int xx = xo + j - 1;
                float v = (xx >= 0 && xx < Ww) ? row[xx] : 0.0f;
                ull vv;
                PACK2_DUP(vv, v);
                const ull* wr = &sw2[(c * 9 + i * 3 + j) * 10];
#pragma unroll
                for (int q = 0; q < 9; q++) {
                    ull w = wr[q];
                    FMA_F32X2(acc2[q], w, vv);
                }
            }
        }
    }

    size_t ob = (size_t)n * NOFF * HW + (size_t)y * Ww + xo;
#pragma unroll
    for (int q = 0; q < 9; q++) {
        float lo, hi;
        UNPACK2(lo, hi, acc2[q]);
        g_off[ob + (size_t)(2 * q) * HW]     = lo;
        g_off[ob + (size_t)(2 * q + 1) * HW] = hi;
    }
}

// ---------------------------------------------------------------------------
// Kernel 2: deformable conv. Block = 256 threads = 256 consecutive x at (n,y).
// 64 output-channel accumulators packed into 32 f32x2 pairs.
// Per tap: stage 64x64 weight slice [c][o] into smem (coalesced), then per
// channel: 4 gathers -> bilinear v, duplicate-pack, 16 LDS.128 (ulonglong2)
// + 32 FFMA2 against broadcast smem weight pairs.
// ---------------------------------------------------------------------------
__global__ void __launch_bounds__(256) deform_conv_kernel(
    const float* __restrict__ xin,
    const float* __restrict__ bdef,
    float* __restrict__ out)
{
    __shared__ __align__(16) ull sw2[2048];   // one tap: [c][o] as 32 pairs/row, 16 KB
    __shared__ ull sb2[32];

    int tid = threadIdx.x;
    float* swf = (float*)sw2;
    if (tid < 32) {
        float lo = bdef[2 * tid];
        float hi = bdef[2 * tid + 1];
        PACK2(sb2[tid], lo, hi);
    }

    int xo = blockIdx.x * 256 + tid;
    int y  = blockIdx.y;
    int n  = blockIdx.z;

    __syncthreads();

    ull acc2[32];
#pragma unroll
    for (int q = 0; q < 32; q++) acc2[q] = sb2[q];

    const float* xb   = xin + (size_t)n * Cc * HW;
    const float* offb = g_off + (size_t)n * NOFF * HW + (size_t)y * Ww + xo;

    for (int t = 0; t < 9; t++) {
        __syncthreads();
#pragma unroll
        for (int m = 0; m < 16; m++)
            swf[m * 256 + tid] = g_wt[t * 4096 + m * 256 + tid];
        __syncthreads();

        int i = t / 3, j = t % 3;
        float dy = offb[(size_t)(2 * t) * HW];
        float dx = offb[(size_t)(2 * t + 1) * HW];
        float py = (float)(y + i - 1) + dy;
        float px = (float)(xo + j - 1) + dx;

        float fy = floorf(py), fx = floorf(px);
        float wy1 = py - fy, wx1 = px - fx;
        float wy0 = 1.0f - wy1, wx0 = 1.0f - wx1;
        int iy0 = (int)fy, ix0 = (int)fx;
        int iy1 = iy0 + 1, ix1 = ix0 + 1;

        float gy0 = (iy0 >= 0 && iy0 < Hh) ? wy0 : 0.0f;
        float gy1 = (iy1 >= 0 && iy1 < Hh) ? wy1 : 0.0f;
        float gx0 = (ix0 >= 0 && ix0 < Ww) ? wx0 : 0.0f;
        float gx1 = (ix1 >= 0 && ix1 < Ww) ? wx1 : 0.0f;
        float c00 = gy0 * gx0, c01 = gy0 * gx1;
        float c10 = gy1 * gx0, c11 = gy1 * gx1;

        int yc0 = min(max(iy0, 0), Hh - 1), yc1 = min(max(iy1, 0), Hh - 1);
        int xc0 = min(max(ix0, 0), Ww - 1), xc1 = min(max(ix1, 0), Ww - 1);
        int o00 = yc0 * Ww + xc0, o01 = yc0 * Ww + xc1;
        int o10 = yc1 * Ww + xc0, o11 = yc1 * Ww + xc1;

        const float* p = xb;
        for (int c = 0; c < Cc; c++) {
            float v;
            v = c00 * p[o00];
            v = fmaf(c01, p[o01], v);
            v = fmaf(c10, p[o10], v);
            v = fmaf(c11, p[o11], v);

            ull vv;
            PACK2_DUP(vv, v);

            const ulonglong2* wv = (const ulonglong2*)(sw2 + (c << 5));
#pragma unroll
            for (int q = 0; q < 16; q++) {
                ulonglong2 w = wv[q];
                FMA_F32X2(acc2[2 * q],     w.x, vv);
                FMA_F32X2(acc2[2 * q + 1], w.y, vv);
            }
            p += HW;
        }
    }

    size_t ob = (size_t)n * CoN * HW + (size_t)y * Ww + xo;
#pragma unroll
    for (int q = 0; q < 32; q++) {
        float lo, hi;
        UNPACK2(lo, hi, acc2[q]);
        out[ob + (size_t)(2 * q) * HW]     = lo;
        out[ob + (size_t)(2 * q + 1) * HW] = hi;
    }
}

// ---------------------------------------------------------------------------
extern "C" void kernel_launch(void* const* d_in, const int* in_sizes, int n_in,
                              void* d_out, int out_size)
{
    const float* x    = (const float*)d_in[0];
    const float* woff = (const float*)d_in[1];
    const float* boff = (const float*)d_in[2];
    const float* wdef = (const float*)d_in[3];
    const float* bdef = (const float*)d_in[4];
    float* out = (float*)d_out;

    wt_transpose_kernel<<<(9 * 64 * 64 + 255) / 256, 256>>>(wdef);
    offset_conv_kernel<<<dim3(Ww / 128, Hh, Nn), 128>>>(x, woff, boff);
    deform_conv_kernel<<<dim3(Ww / 256, Hh, Nn), 256>>>(x, bdef, out);
}

// round 3
// speedup vs baseline: 1.6263x; 1.6263x over previous
#include <cuda_runtime.h>
#include <cuda_bf16.h>

#define Nn  8
#define Cc  64
#define Hh  128
#define Ww  512
#define CoN 64
#define HW  (Hh * Ww)      // 65536
#define NOFF 18
#define SSTR 69            // smem row stride (floats) for the sample tile

// Scratch (no allocations allowed): offsets, and precomputed tf32 B-fragments.
__device__ float  g_off[(size_t)Nn * NOFF * HW];   // ~36 MB
__device__ float2 g_wfrag[9 * 8 * 8 * 32];         // [t][k][ni][lane] = (b0,b1)

__device__ __forceinline__ unsigned f2tf32(float v) {
    unsigned u;
    asm("cvt.rna.tf32.f32 %0, %1;" : "=r"(u) : "f"(v));
    return u;
}

// ---------------------------------------------------------------------------
// Kernel 0: build per-(tap,kstep,nfrag,lane) B fragments for m16n8k8 tf32.
// B[c][o] = w_def[o][c][t];  b0: row c = 8k + lane%4, col o = 8ni + lane/4;
// b1: row c+4, same col. Stored so a warp's 32 lanes read 256B contiguously.
// ---------------------------------------------------------------------------
__global__ void wfrag_kernel(const float* __restrict__ wdef) {
    int idx = blockIdx.x * 256 + threadIdx.x;
    if (idx >= 9 * 8 * 8 * 32) return;
    int lane = idx & 31;
    int ni   = (idx >> 5) & 7;
    int k    = (idx >> 8) & 7;
    int t    = idx >> 11;
    int c = 8 * k + (lane & 3);
    int o = 8 * ni + (lane >> 2);
    float b0 = wdef[(o * 64 + c) * 9 + t];
    float b1 = wdef[(o * 64 + c + 4) * 9 + t];
    g_wfrag[idx] = make_float2(__uint_as_float(f2tf32(b0)),
                               __uint_as_float(f2tf32(b1)));
}

// ---------------------------------------------------------------------------
// Kernel 1: offset-predicting 3x3 conv (C=64 -> 18). Round-1 scalar version
// (known good). 18 fp32 accumulators, weights in smem stride-20.
// ---------------------------------------------------------------------------
__global__ void __launch_bounds__(128) offset_conv_kernel(
    const float* __restrict__ xin,
    const float* __restrict__ woff,
    const float* __restrict__ boff)
{
    __shared__ __align__(16) float sw[576 * 20];
    int tid = threadIdx.x;

    for (int m = tid; m < 18 * 576; m += 128) {
        int t = m / 576;
        int r = m - t * 576;
        sw[r * 20 + t] = woff[m];
    }
    __syncthreads();

    int xo = blockIdx.x * 128 + tid;
    int y  = blockIdx.y;
    int n  = blockIdx.z;

    float acc[18];
#pragma unroll
    for (int t = 0; t < 18; t++) acc[t] = __ldg(&boff[t]);

    const float* xb = xin + (size_t)n * Cc * HW;

    for (int c = 0; c < Cc; c++) {
        const float* xc = xb + c * HW;
#pragma unroll
        for (int i = 0; i < 3; i++) {
            int yy = y + i - 1;
            if (yy < 0 || yy >= Hh) continue;
            const float* row = xc + yy * Ww;
#pragma unroll
            for (int j = 0; j < 3; j++) {
                int xx = xo + j - 1;
                float v = (xx >= 0 && xx < Ww) ? row[xx] : 0.0f;
                const float* wr = &sw[(c * 9 + i * 3 + j) * 20];
                const float4* w4p = (const float4*)wr;
                float4 w0 = w4p[0], w1 = w4p[1], w2 = w4p[2], w3 = w4p[3];
                float2 w4 = *(const float2*)(wr + 16);
                acc[0]  = fmaf(w0.x, v, acc[0]);
                acc[1]  = fmaf(w0.y, v, acc[1]);
                acc[2]  = fmaf(w0.z, v, acc[2]);
                acc[3]  = fmaf(w0.w, v, acc[3]);
                acc[4]  = fmaf(w1.x, v, acc[4]);
                acc[5]  = fmaf(w1.y, v, acc[5]);
                acc[6]  = fmaf(w1.z, v, acc[6]);
                acc[7]  = fmaf(w1.w, v, acc[7]);
                acc[8]  = fmaf(w2.x, v, acc[8]);
                acc[9]  = fmaf(w2.y, v, acc[9]);
                acc[10] = fmaf(w2.z, v, acc[10]);
                acc[11] = fmaf(w2.w, v, acc[11]);
                acc[12] = fmaf(w3.x, v, acc[12]);
                acc[13] = fmaf(w3.y, v, acc[13]);
                acc[14] = fmaf(w3.z, v, acc[14]);
                acc[15] = fmaf(w3.w, v, acc[15]);
                acc[16] = fmaf(w4.x, v, acc[16]);
                acc[17] = fmaf(w4.y, v, acc[17]);
            }
        }
    }

    size_t ob = (size_t)n * NOFF * HW + (size_t)y * Ww + xo;
#pragma unroll
    for (int t = 0; t < 18; t++) g_off[ob + (size_t)t * HW] = acc[t];
}

// ---------------------------------------------------------------------------
// Kernel 2: deformable conv via tf32 tensor MMA.
// CTA = 128 threads = 128 consecutive x at (n,y). Per tap:
//   phase 1: each thread bilinear-samples its pixel for 64 channels -> smem
//            (converted to tf32)
//   phase 2: 4 warps, warp tile M=32 pix x N=64 och, K=64 via 8 k-steps of
//            mma.sync.m16n8k8 (A from smem, B fragments via coalesced LDG.64)
// Accumulators (fp32) persist across the 9 taps; bias folded into init.
// ---------------------------------------------------------------------------
__global__ void __launch_bounds__(128) deform_mma_kernel(
    const float* __restrict__ xin,
    const float* __restrict__ bdef,
    float* __restrict__ out)
{
    __shared__ float sS[128 * SSTR];   // 35.3 KB sample tile [pix][c]

    int tid  = threadIdx.x;
    int lane = tid & 31;
    int warp = tid >> 5;
    int gr   = lane >> 2;     // lane/4
    int tc   = lane & 3;      // lane%4

    int x0 = blockIdx.x * 128;
    int y  = blockIdx.y;
    int n  = blockIdx.z;
    int xg = x0 + tid;

    // init accumulators with bias
    float acc[2][8][4];
#pragma unroll
    for (int ni = 0; ni < 8; ni++) {
        float blo = __ldg(&bdef[8 * ni + 2 * tc]);
        float bhi = __ldg(&bdef[8 * ni + 2 * tc + 1]);
#pragma unroll
        for (int mi = 0; mi < 2; mi++) {
            acc[mi][ni][0] = blo; acc[mi][ni][1] = bhi;
            acc[mi][ni][2] = blo; acc[mi][ni][3] = bhi;
        }
    }

    const float* xb   = xin + (size_t)n * Cc * HW;
    const float* offb = g_off + (size_t)n * NOFF * HW + (size_t)y * Ww + xg;

    for (int t = 0; t < 9; t++) {
        // ---- phase 1: bilinear sample fill ----
        float dy = offb[(size_t)(2 * t) * HW];
        float dx = offb[(size_t)(2 * t + 1) * HW];
        int i = t / 3, j = t % 3;
        float py = (float)(y + i - 1) + dy;
        float px = (float)(xg + j - 1) + dx;

        float fy = floorf(py), fx = floorf(px);
        float wy1 = py - fy, wx1 = px - fx;
        float wy0 = 1.0f - wy1, wx0 = 1.0f - wx1;
        int iy0 = (int)fy, ix0 = (int)fx;
        int iy1 = iy0 + 1, ix1 = ix0 + 1;

        float gy0 = (iy0 >= 0 && iy0 < Hh) ? wy0 : 0.0f;
        float gy1 = (iy1 >= 0 && iy1 < Hh) ? wy1 : 0.0f;
        float gx0 = (ix0 >= 0 && ix0 < Ww) ? wx0 : 0.0f;
        float gx1 = (ix1 >= 0 && ix1 < Ww) ? wx1 : 0.0f;
        float c00 = gy0 * gx0, c01 = gy0 * gx1;
        float c10 = gy1 * gx0, c11 = gy1 * gx1;

        int yc0 = min(max(iy0, 0), Hh - 1), yc1 = min(max(iy1, 0), Hh - 1);
        int xc0 = min(max(ix0, 0), Ww - 1), xc1 = min(max(ix1, 0), Ww - 1);
        int o00 = yc0 * Ww + xc0, o01 = yc0 * Ww + xc1;
        int o10 = yc1 * Ww + xc0, o11 = yc1 * Ww + xc1;

        __syncthreads();   // previous tap's MMA reads finished
        {
            float* srow = sS + tid * SSTR;
            const float* p = xb;
#pragma unroll 4
            for (int c = 0; c < Cc; c++) {
                float v;
                v = c00 * p[o00];
                v = fmaf(c01, p[o01], v);
                v = fmaf(c10, p[o10], v);
                v = fmaf(c11, p[o11], v);
                srow[c] = __uint_as_float(f2tf32(v));
                p += HW;
            }
        }
        __syncthreads();

        // ---- phase 2: tensor MMA over this tap's K=64 ----
        const float2* wf = g_wfrag + (size_t)t * 8 * 8 * 32;
#pragma unroll
        for (int k = 0; k < 8; k++) {
            unsigned a[2][4];
#pragma unroll
            for (int mi = 0; mi < 2; mi++) {
                const float* base = sS + (warp * 32 + mi * 16 + gr) * SSTR + 8 * k + tc;
                a[mi][0] = __float_as_uint(base[0]);
                a[mi][1] = __float_as_uint(base[8 * SSTR]);
                a[mi][2] = __float_as_uint(base[4]);
                a[mi][3] = __float_as_uint(base[8 * SSTR + 4]);
            }
#pragma unroll
            for (int ni = 0; ni < 8; ni++) {
                float2 b = __ldg(&wf[(k * 8 + ni) * 32 + lane]);
                unsigned b0 = __float_as_uint(b.x);
                unsigned b1 = __float_as_uint(b.y);
#pragma unroll
                for (int mi = 0; mi < 2; mi++) {
                    asm volatile(
                        "mma.sync.aligned.m16n8k8.row.col.f32.tf32.tf32.f32 "
                        "{%0,%1,%2,%3}, {%4,%5,%6,%7}, {%8,%9}, {%0,%1,%2,%3};"
                        : "+f"(acc[mi][ni][0]), "+f"(acc[mi][ni][1]),
                          "+f"(acc[mi][ni][2]), "+f"(acc[mi][ni][3])
                        : "r"(a[mi][0]), "r"(a[mi][1]), "r"(a[mi][2]), "r"(a[mi][3]),
                          "r"(b0), "r"(b1));
                }
            }
        }
    }

    // ---- epilogue: scatter accumulators to NCHW output ----
    size_t ob = (size_t)n * CoN * HW + (size_t)y * Ww + x0;
#pragma unroll
    for (int ni = 0; ni < 8; ni++) {
        int o = 8 * ni + 2 * tc;
#pragma unroll
        for (int mi = 0; mi < 2; mi++) {
            int pr = warp * 32 + mi * 16 + gr;
            out[ob + (size_t)o * HW + pr]           = acc[mi][ni][0];
            out[ob + (size_t)(o + 1) * HW + pr]     = acc[mi][ni][1];
            out[ob + (size_t)o * HW + pr + 8]       = acc[mi][ni][2];
            out[ob + (size_t)(o + 1) * HW + pr + 8] = acc[mi][ni][3];
        }
    }
}

// ---------------------------------------------------------------------------
extern "C" void kernel_launch(void* const* d_in, const int* in_sizes, int n_in,
                              void* d_out, int out_size)
{
    const float* x    = (const float*)d_in[0];
    const float* woff = (const float*)d_in[1];
    const float* boff = (const float*)d_in[2];
    const float* wdef = (const float*)d_in[3];
    const float* bdef = (const float*)d_in[4];
    float* out = (float*)d_out;

    wfrag_kernel<<<(9 * 8 * 8 * 32 + 255) / 256, 256>>>(wdef);
    offset_conv_kernel<<<dim3(Ww / 128, Hh, Nn), 128>>>(x, woff, boff);
    deform_mma_kernel<<<dim3(Ww / 128, Hh, Nn), 128>>>(x, bdef, out);
}

// round 4
// speedup vs baseline: 2.0903x; 1.2853x over previous
#include <cuda_runtime.h>
#include <cuda_bf16.h>

#define Nn  8
#define Cc  64
#define Hh  128
#define Ww  512
#define CoN 64
#define HW  (Hh * Ww)      // 65536
#define NOFF 18
#define SSTR 69            // smem row stride (floats) for deform sample tile
#define XSTR 136           // smem row stride (floats) for offset x-tile

// Scratch: offsets, deform tf32 B-frags, offset-conv tf32 B-frags.
__device__ float  g_off[(size_t)Nn * NOFF * HW];   // ~36 MB
__device__ float2 g_wfrag[9 * 8 * 8 * 32];         // deform: [t][k][ni][lane]
__device__ float2 g_wofrag[72 * 3 * 32];           // offset: [kstep][ni][lane]

__device__ __forceinline__ unsigned f2tf32(float v) {
    unsigned u;
    asm("cvt.rna.tf32.f32 %0, %1;" : "=r"(u) : "f"(v));
    return u;
}

// ---------------------------------------------------------------------------
// Kernel 0a: deform B fragments (m16n8k8 tf32), as in Round 3.
// ---------------------------------------------------------------------------
__global__ void wfrag_kernel(const float* __restrict__ wdef) {
    int idx = blockIdx.x * 256 + threadIdx.x;
    if (idx >= 9 * 8 * 8 * 32) return;
    int lane = idx & 31;
    int ni   = (idx >> 5) & 7;
    int k    = (idx >> 8) & 7;
    int t    = idx >> 11;
    int c = 8 * k + (lane & 3);
    int o = 8 * ni + (lane >> 2);
    float b0 = wdef[(o * 64 + c) * 9 + t];
    float b1 = wdef[(o * 64 + c + 4) * 9 + t];
    g_wfrag[idx] = make_float2(__uint_as_float(f2tf32(b0)),
                               __uint_as_float(f2tf32(b1)));
}

// ---------------------------------------------------------------------------
// Kernel 0b: offset-conv B fragments. B[k][oc] with k = c*9 + i*3 + j
// (oc padded 18 -> 24). w_off layout [oc][c][3][3] -> woff[oc*576 + k].
// ---------------------------------------------------------------------------
__global__ void wofrag_kernel(const float* __restrict__ woff) {
    int idx = blockIdx.x * 256 + threadIdx.x;
    if (idx >= 72 * 3 * 32) return;
    int lane = idx & 31;
    int rem  = idx >> 5;
    int ni   = rem % 3;
    int ks   = rem / 3;
    int gr = lane >> 2, tc = lane & 3;
    int k0 = 8 * ks + tc;        // 0..571
    int oc = 8 * ni + gr;        // 0..23
    float b0 = (oc < 18) ? woff[oc * 576 + k0]     : 0.0f;
    float b1 = (oc < 18) ? woff[oc * 576 + k0 + 4] : 0.0f;
    g_wofrag[(ks * 3 + ni) * 32 + lane] =
        make_float2(__uint_as_float(f2tf32(b0)), __uint_as_float(f2tf32(b1)));
}

// ---------------------------------------------------------------------------
// Kernel 1: offset conv via tf32 MMA with shifted-view A fragments.
// CTA = 128 px at (n,y). 8 channel-chunks: stage [8c][3row][130col] x-tile
// (tf32) in smem, then 9 k-steps x 3 n-frags x 2 m-frags of m16n8k8.
// A element A[m][k]: k=(c,i,j) -> sx[(c*3+i)*XSTR + m + j]  (pure shift).
// ---------------------------------------------------------------------------
__global__ void __launch_bounds__(128) offset_mma_kernel(
    const float* __restrict__ xin,
    const float* __restrict__ boff)
{
    __shared__ float sx[24 * XSTR];   // 13056 B

    int tid  = threadIdx.x;
    int lane = tid & 31;
    int warp = tid >> 5;
    int gr   = lane >> 2;
    int tc   = lane & 3;

    int x0 = blockIdx.x * 128;
    int y  = blockIdx.y;
    int n  = blockIdx.z;

    float acc[2][3][4];
#pragma unroll
    for (int ni = 0; ni < 3; ni++) {
        int oc = 8 * ni + 2 * tc;
        float blo = (oc < 18)     ? __ldg(&boff[oc])     : 0.0f;
        float bhi = (oc + 1 < 18) ? __ldg(&boff[oc + 1]) : 0.0f;
#pragma unroll
        for (int mi = 0; mi < 2; mi++) {
            acc[mi][ni][0] = blo; acc[mi][ni][1] = bhi;
            acc[mi][ni][2] = blo; acc[mi][ni][3] = bhi;
        }
    }

    const float* xb = xin + (size_t)n * Cc * HW;

    for (int ch = 0; ch < 8; ch++) {
        __syncthreads();
        // fill: 8 channels x 3 rows x 130 cols (zero-padded at borders)
        for (int idx = tid; idx < 3120; idx += 128) {
            int c   = idx / 390;
            int r   = idx - 390 * c;
            int i   = r / 130;
            int col = r - 130 * i;
            int yy = y + i - 1;
            int xx = x0 + col - 1;
            float v = 0.0f;
            if (yy >= 0 && yy < Hh && xx >= 0 && xx < Ww)
                v = xb[(size_t)(ch * 8 + c) * HW + yy * Ww + xx];
            sx[(c * 3 + i) * XSTR + col] = __uint_as_float(f2tf32(v));
        }
        __syncthreads();

#pragma unroll
        for (int kk = 0; kk < 9; kk++) {
            int kl = 8 * kk + tc;
            int c0 = kl / 9,  t0 = kl - 9 * c0;
            int i0 = t0 / 3,  j0 = t0 - 3 * i0;
            int kl2 = kl + 4;
            int c1 = kl2 / 9, t1 = kl2 - 9 * c1;
            int i1 = t1 / 3,  j1 = t1 - 3 * i1;
            int off0 = (c0 * 3 + i0) * XSTR + j0;
            int off1 = (c1 * 3 + i1) * XSTR + j1;

            const float2* wf = g_wofrag + (size_t)(ch * 9 + kk) * 96;
            float2 bfr[3];
#pragma unroll
            for (int ni = 0; ni < 3; ni++) bfr[ni] = __ldg(&wf[ni * 32 + lane]);

#pragma unroll
            for (int mi = 0; mi < 2; mi++) {
                int m = warp * 32 + mi * 16 + gr;
                unsigned a0 = __float_as_uint(sx[off0 + m]);
                unsigned a1 = __float_as_uint(sx[off0 + m + 8]);
                unsigned a2 = __float_as_uint(sx[off1 + m]);
                unsigned a3 = __float_as_uint(sx[off1 + m + 8]);
#pragma unroll
                for (int ni = 0; ni < 3; ni++) {
                    unsigned b0 = __float_as_uint(bfr[ni].x);
                    unsigned b1 = __float_as_uint(bfr[ni].y);
                    asm volatile(
                        "mma.sync.aligned.m16n8k8.row.col.f32.tf32.tf32.f32 "
                        "{%0,%1,%2,%3}, {%4,%5,%6,%7}, {%8,%9}, {%0,%1,%2,%3};"
                        : "+f"(acc[mi][ni][0]), "+f"(acc[mi][ni][1]),
                          "+f"(acc[mi][ni][2]), "+f"(acc[mi][ni][3])
                        : "r"(a0), "r"(a1), "r"(a2), "r"(a3),
                          "r"(b0), "r"(b1));
                }
            }
        }
    }

    // epilogue: write 18 valid output channels to g_off [n][t][y][x]
    size_t ob = (size_t)n * NOFF * HW + (size_t)y * Ww + x0;
#pragma unroll
    for (int ni = 0; ni < 3; ni++) {
        int oc = 8 * ni + 2 * tc;
#pragma unroll
        for (int mi = 0; mi < 2; mi++) {
            int pr = warp * 32 + mi * 16 + gr;
            if (oc < 18) {
                g_off[ob + (size_t)oc * HW + pr]     = acc[mi][ni][0];
                g_off[ob + (size_t)oc * HW + pr + 8] = acc[mi][ni][2];
            }
            if (oc + 1 < 18) {
                g_off[ob + (size_t)(oc + 1) * HW + pr]     = acc[mi][ni][1];
                g_off[ob + (size_t)(oc + 1) * HW + pr + 8] = acc[mi][ni][3];
            }
        }
    }
}

// ---------------------------------------------------------------------------
// Kernel 2: deformable conv via tf32 tensor MMA (unchanged from Round 3).
// ---------------------------------------------------------------------------
__global__ void __launch_bounds__(128) deform_mma_kernel(
    const float* __restrict__ xin,
    const float* __restrict__ bdef,
    float* __restrict__ out)
{
    __shared__ float sS[128 * SSTR];   // 35.3 KB sample tile [pix][c]

    int tid  = threadIdx.x;
    int lane = tid & 31;
    int warp = tid >> 5;
    int gr   = lane >> 2;
    int tc   = lane & 3;

    int x0 = blockIdx.x * 128;
    int y  = blockIdx.y;
    int n  = blockIdx.z;
    int xg = x0 + tid;

    float acc[2][8][4];
#pragma unroll
    for (int ni = 0; ni < 8; ni++) {
        float blo = __ldg(&bdef[8 * ni + 2 * tc]);
        float bhi = __ldg(&bdef[8 * ni + 2 * tc + 1]);
#pragma unroll
        for (int mi = 0; mi < 2; mi++) {
            acc[mi][ni][0] = blo; acc[mi][ni][1] = bhi;
            acc[mi][ni][2] = blo; acc[mi][ni][3] = bhi;
        }
    }

    const float* xb   = xin + (size_t)n * Cc * HW;
    const float* offb = g_off + (size_t)n * NOFF * HW + (size_t)y * Ww + xg;

    for (int t = 0; t < 9; t++) {
        float dy = offb[(size_t)(2 * t) * HW];
        float dx = offb[(size_t)(2 * t + 1) * HW];
        int i = t / 3, j = t % 3;
        float py = (float)(y + i - 1) + dy;
        float px = (float)(xg + j - 1) + dx;

        float fy = floorf(py), fx = floorf(px);
        float wy1 = py - fy, wx1 = px - fx;
        float wy0 = 1.0f - wy1, wx0 = 1.0f - wx1;
        int iy0 = (int)fy, ix0 = (int)fx;
        int iy1 = iy0 + 1, ix1 = ix0 + 1;

        float gy0 = (iy0 >= 0 && iy0 < Hh) ? wy0 : 0.0f;
        float gy1 = (iy1 >= 0 && iy1 < Hh) ? wy1 : 0.0f;
        float gx0 = (ix0 >= 0 && ix0 < Ww) ? wx0 : 0.0f;
        float gx1 = (ix1 >= 0 && ix1 < Ww) ? wx1 : 0.0f;
        float c00 = gy0 * gx0, c01 = gy0 * gx1;
        float c10 = gy1 * gx0, c11 = gy1 * gx1;

        int yc0 = min(max(iy0, 0), Hh - 1), yc1 = min(max(iy1, 0), Hh - 1);
        int xc0 = min(max(ix0, 0), Ww - 1), xc1 = min(max(ix1, 0), Ww - 1);
        int o00 = yc0 * Ww + xc0, o01 = yc0 * Ww + xc1;
        int o10 = yc1 * Ww + xc0, o11 = yc1 * Ww + xc1;

        __syncthreads();
        {
            float* srow = sS + tid * SSTR;
            const float* p = xb;
#pragma unroll 4
            for (int c = 0; c < Cc; c++) {
                float v;
                v = c00 * p[o00];
                v = fmaf(c01, p[o01], v);
                v = fmaf(c10, p[o10], v);
                v = fmaf(c11, p[o11], v);
                srow[c] = __uint_as_float(f2tf32(v));
                p += HW;
            }
        }
        __syncthreads();

        const float2* wf = g_wfrag + (size_t)t * 8 * 8 * 32;
#pragma unroll
        for (int k = 0; k < 8; k++) {
            unsigned a[2][4];
#pragma unroll
            for (int mi = 0; mi < 2; mi++) {
                const float* base = sS + (warp * 32 + mi * 16 + gr) * SSTR + 8 * k + tc;
                a[mi][0] = __float_as_uint(base[0]);
                a[mi][1] = __float_as_uint(base[8 * SSTR]);
                a[mi][2] = __float_as_uint(base[4]);
                a[mi][3] = __float_as_uint(base[8 * SSTR + 4]);
            }
#pragma unroll
            for (int ni = 0; ni < 8; ni++) {
                float2 b = __ldg(&wf[(k * 8 + ni) * 32 + lane]);
                unsigned b0 = __float_as_uint(b.x);
                unsigned b1 = __float_as_uint(b.y);
#pragma unroll
                for (int mi = 0; mi < 2; mi++) {
                    asm volatile(
                        "mma.sync.aligned.m16n8k8.row.col.f32.tf32.tf32.f32 "
                        "{%0,%1,%2,%3}, {%4,%5,%6,%7}, {%8,%9}, {%0,%1,%2,%3};"
                        : "+f"(acc[mi][ni][0]), "+f"(acc[mi][ni][1]),
                          "+f"(acc[mi][ni][2]), "+f"(acc[mi][ni][3])
                        : "r"(a[mi][0]), "r"(a[mi][1]), "r"(a[mi][2]), "r"(a[mi][3]),
                          "r"(b0), "r"(b1));
                }
            }
        }
    }

    size_t ob = (size_t)n * CoN * HW + (size_t)y * Ww + x0;
#pragma unroll
    for (int ni = 0; ni < 8; ni++) {
        int o = 8 * ni + 2 * tc;
#pragma unroll
        for (int mi = 0; mi < 2; mi++) {
            int pr = warp * 32 + mi * 16 + gr;
            out[ob + (size_t)o * HW + pr]           = acc[mi][ni][0];
            out[ob + (size_t)(o + 1) * HW + pr]     = acc[mi][ni][1];
            out[ob + (size_t)o * HW + pr + 8]       = acc[mi][ni][2];
            out[ob + (size_t)(o + 1) * HW + pr + 8] = acc[mi][ni][3];
        }
    }
}

// ---------------------------------------------------------------------------
extern "C" void kernel_launch(void* const* d_in, const int* in_sizes, int n_in,
                              void* d_out, int out_size)
{
    const float* x    = (const float*)d_in[0];
    const float* woff = (const float*)d_in[1];
    const float* boff = (const float*)d_in[2];
    const float* wdef = (const float*)d_in[3];
    const float* bdef = (const float*)d_in[4];
    float* out = (float*)d_out;

    wfrag_kernel<<<(9 * 8 * 8 * 32 + 255) / 256, 256>>>(wdef);
    wofrag_kernel<<<(72 * 3 * 32 + 255) / 256, 256>>>(woff);
    offset_mma_kernel<<<dim3(Ww / 128, Hh, Nn), 128>>>(x, boff);
    deform_mma_kernel<<<dim3(Ww / 128, Hh, Nn), 128>>>(x, bdef, out);
}